// round 15
// baseline (speedup 1.0000x reference)
#include <cuda_runtime.h>

// APMLSparse: x[B,N,3], y[B,M,3] fp32 -> scalar loss. B=4, N=M=4096.
// Per row: d_j = sqrt(max(||x-y_j||^2,1e-12)), e_j=exp(-d_j), Z=sum e_j.
// Kept = d-ascending prefix while exclusive cumulative mass < 0.8*Z (incl.
// crossing entry, p>1e-10 filter). loss += sum_kept e_j*d_j / Z.
//
// R11 = R10 (350us best: 32-bin width-0.5 private banked histogram, 1/64
// sub-bins, ballot compact, penta, O(k^2)) + three shape-preserving cuts:
//  1) complement trick: pass-1 accumulates S_all = sum e*d; compact pays
//     __expf only for EXCLUDED elements (~20%) instead of kept (~80%);
//     kept sum = S_all - excluded sum.
//  2) read-and-clear bin reduces delete both in-row zeroing loops.
//  3) recompact kept arm is a no-op (already in S_all).

#define NTH   512
#define NPT   8            // 4096 / NTH
#define RPC   8
#define MPTS  4096
#define NB    32           // bins per stage (width 0.5 stage 1, 1/64 stage 2)
#define HISTN (NB * NTH)   // 16384 floats = 64 KB (dynamic)
#define CAP   512
#define CAP2  128
#define HIST_BYTES (HISTN * 4)

__global__ void apml_zero_out(float* o) { o[0] = 0.0f; }

__global__ __launch_bounds__(NTH, 2)
void apml_kernel(const float* __restrict__ x, const float* __restrict__ y,
                 float* __restrict__ out)
{
    extern __shared__ float hist[];     // 64 KB private histogram columns
    __shared__ float2 list[CAP];        // 4 KB crossing-window elements
    __shared__ float  l2d[CAP2];        // final band
    __shared__ float  l2e[CAP2];
    __shared__ float  binTot[NB];
    __shared__ float  warpRed[64];
    __shared__ float  s_ctl[8];         // 0:Z 1:T 2:(c1|l2f) 3:h2f 4:mLo 5:l3 6:h3 7:mLo3
    __shared__ int    s_int[2];

    const int tid  = threadIdx.x, lane = tid & 31, wid = tid >> 5;
    const int cpb  = MPTS / RPC;                    // 512
    const int b    = blockIdx.x / cpb;
    const int rowBase = (blockIdx.x % cpb) * RPC;

    // 8 y-points per thread in registers, reused across RPC rows.
    float yx[NPT], yy[NPT], yz[NPT];
    const float* yb = y + (size_t)b * MPTS * 3;
#pragma unroll
    for (int k = 0; k < NPT; k++) {
        int j = k * NTH + tid;
        yx[k] = yb[j * 3 + 0];
        yy[k] = yb[j * 3 + 1];
        yz[k] = yb[j * 3 + 2];
    }

    float4* hist4 = (float4*)hist;

    // Initial histogram zero; read-and-clear reduces keep it clean afterwards.
#pragma unroll
    for (int i = 0; i < HISTN / 4 / NTH; i++)
        hist4[tid + i * NTH] = make_float4(0.f, 0.f, 0.f, 0.f);

    float ctaAcc = 0.0f;
    __syncthreads();

    for (int r = 0; r < RPC; r++) {
        const float* xp = x + ((size_t)b * MPTS + rowBase + r) * 3;
        const float x0 = __ldg(xp + 0);
        const float x1 = __ldg(xp + 1);
        const float x2 = __ldg(xp + 2);

        // ---- pass 1 fused with stage-1 fill: bins of width 0.5 over [0,16) ----
        float dreg[NPT];
        float sAll = 0.0f;                          // sum e*d over ALL elements
#pragma unroll
        for (int k = 0; k < NPT; k++) {
            float dx = x0 - yx[k];
            float dy = x1 - yy[k];
            float dz = x2 - yz[k];
            float sq = fmaf(dx, dx, fmaf(dy, dy, dz * dz));
            sq = fmaxf(sq, 1e-12f);
            float d = sq * rsqrtf(sq);              // sqrt via MUFU.RSQ + FMUL
            dreg[k] = d;
            float e = __expf(-d);
            sAll = fmaf(e, d, sAll);
            int bin = (int)(2.0f * d);              // exact 2^1 scaling
            bin = bin < (NB - 1) ? bin : (NB - 1);  // clamp stray large d
            hist[bin * NTH + tid] += e;             // conflict-free column
        }
        __syncthreads();

        // ---- stage-1 reduce: warp w sums bins 2w, 2w+1 (and clears) ----
#pragma unroll
        for (int q = 0; q < 2; q++) {
            int bb = 2 * wid + q;
            float s = 0.f;
            int base = bb * (NTH / 4);
#pragma unroll
            for (int i = 0; i < NTH / 4 / 32; i++) {
                float4 v = hist4[base + lane + i * 32];
                s += (v.x + v.y) + (v.z + v.w);
                hist4[base + lane + i * 32] = make_float4(0.f, 0.f, 0.f, 0.f);
            }
#pragma unroll
            for (int o = 16; o; o >>= 1) s += __shfl_xor_sync(0xffffffffu, s, o);
            if (lane == 0) binTot[bb] = s;
        }
        __syncthreads();

        // ---- stage-1 scan + pick (warp 0, 32 lanes = 32 bins) ----
        if (wid == 0) {
            float mm = binTot[lane];
            float incl = mm;
#pragma unroll
            for (int o = 1; o < 32; o <<= 1) {
                float t = __shfl_up_sync(0xffffffffu, incl, o);
                if (lane >= o) incl += t;
            }
            float total = __shfl_sync(0xffffffffu, incl, 31);
            float T = 0.8f * total;
            float excl = incl - mm;
            bool cross = (excl < T) && (incl >= T);
            unsigned bal = __ballot_sync(0xffffffffu, cross);
            int c1 = bal ? (__ffs(bal) - 1) : (NB - 1);
            float mlo = __shfl_sync(0xffffffffu, excl, c1);
            if (lane == 0) {
                s_ctl[0] = total;            // Z
                s_ctl[1] = T;
                s_ctl[2] = (float)c1;
                s_ctl[4] = mlo;              // mLo1
                s_int[0] = 0;   // prior-row readers are >=3 barriers upstream
                s_int[1] = 0;
            }
        }
        __syncthreads();
        const float Z    = s_ctl[0];
        const float T    = s_ctl[1];
        const int   c1s  = ((int)s_ctl[2]) << 5;    // c1*32
        const float mLo1 = s_ctl[4];

        // ---- stage-2 fill: 32 sub-bins of width 1/64 over crossing bin ----
#pragma unroll
        for (int k = 0; k < NPT; k++) {
            float d = dreg[k];
            int b2 = (int)(d * 64.0f) - c1s;        // exact: 2^ scalings nest
            if ((unsigned)b2 < (unsigned)NB) {
                float e = __expf(-d);
                hist[b2 * NTH + tid] += e;
            }
        }
        __syncthreads();

        // ---- stage-2 reduce (and clear) ----
#pragma unroll
        for (int q = 0; q < 2; q++) {
            int bb = 2 * wid + q;
            float s = 0.f;
            int base = bb * (NTH / 4);
#pragma unroll
            for (int i = 0; i < NTH / 4 / 32; i++) {
                float4 v = hist4[base + lane + i * 32];
                s += (v.x + v.y) + (v.z + v.w);
                hist4[base + lane + i * 32] = make_float4(0.f, 0.f, 0.f, 0.f);
            }
#pragma unroll
            for (int o = 16; o; o >>= 1) s += __shfl_xor_sync(0xffffffffu, s, o);
            if (lane == 0) binTot[bb] = s;
        }
        __syncthreads();

        // ---- stage-2 scan + pick ----
        if (wid == 0) {
            float mm = binTot[lane];
            float incl = mm;
#pragma unroll
            for (int o = 1; o < 32; o <<= 1) {
                float t = __shfl_up_sync(0xffffffffu, incl, o);
                if (lane >= o) incl += t;
            }
            float excl = incl - mm;
            bool cross = (mLo1 + excl < T) && (mLo1 + incl >= T);
            unsigned bal = __ballot_sync(0xffffffffu, cross);
            int c2 = bal ? (__ffs(bal) - 1) : (NB - 1);   // fp-mismatch fallback
            float mlo2 = mLo1 + __shfl_sync(0xffffffffu, excl, c2);
            if (lane == 0) {
                float l2f = (float)(c1s + c2) * 0.015625f;  // exact fp (/64)
                s_ctl[2] = l2f;
                s_ctl[3] = l2f + 0.015625f;
                s_ctl[4] = mlo2;
            }
        }
        __syncthreads();
        const float l2f  = s_ctl[2];
        const float h2f  = s_ctl[3];
        const float mLo2 = s_ctl[4];

        // ---- compact: EXCLUDED (d>=h2f) accumulate e*d; band -> list ----
        float accAbove = 0.0f;
#pragma unroll
        for (int k = 0; k < NPT; k++) {
            float d = dreg[k];
            bool above = d >= h2f;                  // excluded for sure (~20%)
            bool band  = (!above) && (d >= l2f);    // boundary sub-bin
            if (above) accAbove = fmaf(__expf(-d), d, accAbove);
            unsigned mk = __ballot_sync(0xffffffffu, band);
            if (mk) {
                int leader = __ffs(mk) - 1;
                int base2 = 0;
                if (lane == leader) base2 = atomicAdd(&s_int[0], __popc(mk));
                base2 = __shfl_sync(0xffffffffu, base2, leader);
                if (band) {
                    int idx = base2 + __popc(mk & ((1u << lane) - 1u));
                    float e = __expf(-d);
                    if (idx < CAP) list[idx] = make_float2(d, e);
                    else           accAbove = fmaf(e, d, accAbove); // treat as excluded
                }
            }
        }
        __syncthreads();
        const int cnt = s_int[0] < CAP ? s_int[0] : CAP;

        // ---- one penta round on the ~35-element list ----
        {
            float w  = (h2f - l2f) * 0.2f;
            float u1 = l2f + w, u2 = l2f + 2.f * w, u3 = l2f + 3.f * w, u4 = l2f + 4.f * w;
            float p0 = 0.f, p1 = 0.f, p2 = 0.f, p3 = 0.f;
            for (int i = tid; i < cnt; i += NTH) {
                float2 v = list[i];
                p0 += (v.x < u1) ? v.y : 0.f;
                p1 += (v.x < u2) ? v.y : 0.f;
                p2 += (v.x < u3) ? v.y : 0.f;
                p3 += (v.x < u4) ? v.y : 0.f;
            }
#pragma unroll
            for (int o = 16; o; o >>= 1) {
                p0 += __shfl_xor_sync(0xffffffffu, p0, o);
                p1 += __shfl_xor_sync(0xffffffffu, p1, o);
                p2 += __shfl_xor_sync(0xffffffffu, p2, o);
                p3 += __shfl_xor_sync(0xffffffffu, p3, o);
            }
            if (lane == 0) {
                warpRed[wid] = p0; warpRed[16 + wid] = p1;
                warpRed[32 + wid] = p2; warpRed[48 + wid] = p3;
            }
            __syncthreads();
            if (wid == 0) {
                float s = 0.f;
                if (lane < 4) {
#pragma unroll
                    for (int i = 0; i < 16; i++) s += warpRed[lane * 16 + i];
                }
                float m1 = __shfl_sync(0xffffffffu, s, 0);
                float m2 = __shfl_sync(0xffffffffu, s, 1);
                float m3 = __shfl_sync(0xffffffffu, s, 2);
                float m4 = __shfl_sync(0xffffffffu, s, 3);
                if (lane == 0) {
                    float l = l2f, h = u1, ml = mLo2;
                    if (mLo2 + m1 < T) { l = u1; h = u2; ml = mLo2 + m1;
                      if (mLo2 + m2 < T) { l = u2; h = u3; ml = mLo2 + m2;
                        if (mLo2 + m3 < T) { l = u3; h = u4; ml = mLo2 + m3;
                          if (mLo2 + m4 < T) { l = u4; h = h2f; ml = mLo2 + m4; } } } }
                    s_ctl[5] = l; s_ctl[6] = h; s_ctl[7] = ml;
                }
            }
            __syncthreads();
        }
        const float l3 = s_ctl[5], h3 = s_ctl[6], mLo3 = s_ctl[7];

        // ---- recompact: [h3,h2f) excluded -> accAbove; [l3,h3) -> l2d;
        //      below-l3 kept -> no-op (already counted in sAll) ----
        for (int i = tid; i < cnt; i += NTH) {
            float2 v = list[i];
            if (v.x >= h3) {
                accAbove = fmaf(v.y, v.x, accAbove);
            } else if (v.x >= l3) {
                int idx = atomicAdd(&s_int[1], 1);
                if (idx < CAP2) { l2d[idx] = v.x; l2e[idx] = v.y; }
                else            accAbove = fmaf(v.y, v.x, accAbove); // excluded-safe? no:
                // overflow fallback treats as excluded; CAP2 overflow is ~impossible
            }
        }
        __syncthreads();

        // ---- exact O(k^2): NOT-kept band members -> accAbove ----
        const int   c2n  = s_int[1] < CAP2 ? s_int[1] : CAP2;
        const float Trem = T - mLo3;
        const float eThr = 1e-10f * Z;
        for (int i = tid; i < c2n; i += NTH) {
            float di = l2d[i], ei = l2e[i], rm = 0.f;
            for (int j = 0; j < c2n; j++) {
                float dj = l2d[j];
                rm += ((dj < di) || (dj == di && j < i)) ? l2e[j] : 0.f;
            }
            if (!(rm < Trem && ei > eThr)) accAbove = fmaf(ei, di, accAbove);
        }

        // ---- row reduce of (kept sum) = sAll - accAbove ----
        float acc = sAll - accAbove;
#pragma unroll
        for (int o = 16; o; o >>= 1) acc += __shfl_xor_sync(0xffffffffu, acc, o);
        if (lane == 0) warpRed[wid] = acc;
        __syncthreads();
        if (tid == 0) {
            float tot = 0.f;
#pragma unroll
            for (int i = 0; i < 16; i++) tot += warpRed[i];
            ctaAcc += tot / Z;
        }
        __syncthreads();   // protect warpRed/hist before next row
    }

    if (tid == 0) atomicAdd(out, ctaAcc);
}

extern "C" void kernel_launch(void* const* d_in, const int* in_sizes, int n_in,
                              void* d_out, int out_size)
{
    const float* x = (const float*)d_in[0];
    const float* y = (const float*)d_in[1];
    float* out = (float*)d_out;

    cudaFuncSetAttribute(apml_kernel,
                         cudaFuncAttributeMaxDynamicSharedMemorySize, HIST_BYTES);

    apml_zero_out<<<1, 1>>>(out);
    const int grid = (4 * MPTS) / RPC;   // 2048 CTAs
    apml_kernel<<<grid, NTH, HIST_BYTES>>>(x, y, out);
}